// round 8
// baseline (speedup 1.0000x reference)
#include <cuda_runtime.h>
#include <cuda_bf16.h>
#include <math.h>

// ---------------- problem constants ----------------
#define B_    512
#define A_    8
#define NN    42
#define NIN   32
#define H     128
#define BFN   3
#define NH    4
#define LL    2
#define FF    256
#define OUTD  128
#define EE    41
#define HD    32
#define FB    (B_*A_)        // 4096
#define TT    (FB*NN)        // 172032

// ---------------- scratch (no allocs allowed) ----------------
__device__ float g_x[(size_t)TT*H];        // activations
__device__ float g_pos[(size_t)TT*H];      // pos / attn-out / ff2-out
__device__ float g_qkv[(size_t)TT*3*H];    // qkv / ff-hidden / oproj-out
__device__ float g_fin[(size_t)FB*OUTD];   // final pre-LN accumulator

// ---------------- positional encoding (single topological pass) ----------------
// Edge e has child = e+1 and parent <= e, so edge order is topological.
__global__ __launch_bounds__(128) void pos_kernel(const int* __restrict__ adj,
                                                  const int* __restrict__ order,
                                                  float* __restrict__ pos)
{
    int fb = blockIdx.x;
    int h  = threadIdx.x;    // 0..127  (owns column h for all nodes)
    __shared__ int   par[EE];
    __shared__ int   eidx[EE];     // one-hot index per edge
    __shared__ int   dep[NN];
    __shared__ float ps[NN][H];

    if (h < EE) {
        const int* e = &adj[((size_t)fb*EE + h)*3];
        int p = e[0] - fb*NN;          // local parent index
        par[h] = p;
        int s = e[2] + 1; s = min(max(s, 0), BFN-1);
        eidx[h] = s;                   // depth added below by thread 0
    }
    __syncthreads();
    if (h == 0) {
        dep[0] = 0;
        for (int e = 0; e < EE; e++) {
            int p  = par[e];
            int dp = dep[p];
            dep[e + 1] = dp + 1;
            eidx[e] = dp * BFN + eidx[e];     // < 126 always
        }
    }
    ps[0][h] = 0.f;
    __syncthreads();

    // each thread walks its own column; no barriers needed
#pragma unroll 1
    for (int e = 0; e < EE; e++) {
        float v = ps[par[e]][h] + ((h == eidx[e]) ? 1.f : 0.f);
        ps[e + 1][h] = v;
    }
    for (int n = 0; n < NN; n++)
        pos[((size_t)(fb*NN + n))*H + h] = ps[n][h];
}

// ---------------- TF32 tensor-core GEMM  C = A[M,K] @ W[N,K]^T ----------------
__device__ __forceinline__ unsigned f2tf(float f)
{
    unsigned u;
    asm("cvt.rna.tf32.f32 %0, %1;" : "=r"(u) : "f"(f));
    return u;
}

#define BM  128
#define BN  128
#define BK  16
#define LDK 20       // padded k-stride (words): frag LDS conflict-free

#define EPI_BIAS   0
#define EPI_RELU   1
#define EPI_ADD    2
#define EPI_ATOMIC 3

template<int EPI>
__global__ __launch_bounds__(256)
void gemm_tc(const float* __restrict__ Ag, const float* __restrict__ Wg,
             const float* __restrict__ bias, const float* __restrict__ resid,
             float* __restrict__ Cg, int M, int N, int K)
{
    __shared__ unsigned As[2][BM][LDK];
    __shared__ unsigned Bs[2][BN][LDK];

    int m0 = blockIdx.x * BM;
    int n0 = blockIdx.y * BN;
    int per = K / gridDim.z;
    int ks  = blockIdx.z * per;
    int ke  = ks + per;

    int tid  = threadIdx.x;
    int lane = tid & 31;
    int warp = tid >> 5;
    int wm = warp >> 2;
    int wn = warp & 3;
    int gid = lane >> 2;
    int tg  = lane & 3;
    int lrow = tid >> 1;
    int lcol = (tid & 1) * 8;

    float acc[4][4][4];
#pragma unroll
    for (int i = 0; i < 4; i++)
#pragma unroll
        for (int j = 0; j < 4; j++)
#pragma unroll
            for (int k = 0; k < 4; k++) acc[i][j][k] = 0.f;

    const float* Ap = Ag + (size_t)(m0 + lrow) * K + lcol;
    const float* Wp = Wg + (size_t)(n0 + lrow) * K + lcol;

    float4 av0, av1, wv0, wv1;

    av0 = *(const float4*)(Ap + ks);
    av1 = *(const float4*)(Ap + ks + 4);
    wv0 = *(const float4*)(Wp + ks);
    wv1 = *(const float4*)(Wp + ks + 4);
    *(uint4*)&As[0][lrow][lcol]     = make_uint4(f2tf(av0.x), f2tf(av0.y), f2tf(av0.z), f2tf(av0.w));
    *(uint4*)&As[0][lrow][lcol + 4] = make_uint4(f2tf(av1.x), f2tf(av1.y), f2tf(av1.z), f2tf(av1.w));
    *(uint4*)&Bs[0][lrow][lcol]     = make_uint4(f2tf(wv0.x), f2tf(wv0.y), f2tf(wv0.z), f2tf(wv0.w));
    *(uint4*)&Bs[0][lrow][lcol + 4] = make_uint4(f2tf(wv1.x), f2tf(wv1.y), f2tf(wv1.z), f2tf(wv1.w));
    __syncthreads();

    int cur = 0;
    for (int kt = ks; kt < ke; kt += BK) {
        bool more = (kt + BK) < ke;
        if (more) {
            av0 = *(const float4*)(Ap + kt + BK);
            av1 = *(const float4*)(Ap + kt + BK + 4);
            wv0 = *(const float4*)(Wp + kt + BK);
            wv1 = *(const float4*)(Wp + kt + BK + 4);
        }

#pragma unroll
        for (int k2 = 0; k2 < 2; k2++) {
            int kk = k2 * 8;
            unsigned af[4][4], bf[4][2];
#pragma unroll
            for (int mt = 0; mt < 4; mt++) {
                int r = wm*64 + mt*16 + gid;
                af[mt][0] = As[cur][r    ][kk + tg];
                af[mt][1] = As[cur][r + 8][kk + tg];
                af[mt][2] = As[cur][r    ][kk + tg + 4];
                af[mt][3] = As[cur][r + 8][kk + tg + 4];
            }
#pragma unroll
            for (int nt = 0; nt < 4; nt++) {
                int c = wn*32 + nt*8 + gid;
                bf[nt][0] = Bs[cur][c][kk + tg];
                bf[nt][1] = Bs[cur][c][kk + tg + 4];
            }
#pragma unroll
            for (int mt = 0; mt < 4; mt++)
#pragma unroll
                for (int nt = 0; nt < 4; nt++) {
                    asm volatile(
                        "mma.sync.aligned.m16n8k8.row.col.f32.tf32.tf32.f32 "
                        "{%0,%1,%2,%3}, {%4,%5,%6,%7}, {%8,%9}, {%0,%1,%2,%3};\n"
                        : "+f"(acc[mt][nt][0]), "+f"(acc[mt][nt][1]),
                          "+f"(acc[mt][nt][2]), "+f"(acc[mt][nt][3])
                        : "r"(af[mt][0]), "r"(af[mt][1]), "r"(af[mt][2]), "r"(af[mt][3]),
                          "r"(bf[nt][0]), "r"(bf[nt][1]));
                }
        }

        if (more) {
            int nxt = cur ^ 1;
            *(uint4*)&As[nxt][lrow][lcol]     = make_uint4(f2tf(av0.x), f2tf(av0.y), f2tf(av0.z), f2tf(av0.w));
            *(uint4*)&As[nxt][lrow][lcol + 4] = make_uint4(f2tf(av1.x), f2tf(av1.y), f2tf(av1.z), f2tf(av1.w));
            *(uint4*)&Bs[nxt][lrow][lcol]     = make_uint4(f2tf(wv0.x), f2tf(wv0.y), f2tf(wv0.z), f2tf(wv0.w));
            *(uint4*)&Bs[nxt][lrow][lcol + 4] = make_uint4(f2tf(wv1.x), f2tf(wv1.y), f2tf(wv1.z), f2tf(wv1.w));
            __syncthreads();
        }
        cur ^= 1;
    }

#pragma unroll
    for (int mt = 0; mt < 4; mt++) {
#pragma unroll
        for (int nt = 0; nt < 4; nt++) {
            int r = m0 + wm*64 + mt*16 + gid;
            int c = n0 + wn*32 + nt*8 + 2*tg;
            if constexpr (EPI == EPI_ATOMIC) {
                atomicAdd(&Cg[(size_t)r*N + c],         acc[mt][nt][0]);
                atomicAdd(&Cg[(size_t)r*N + c + 1],     acc[mt][nt][1]);
                atomicAdd(&Cg[(size_t)(r+8)*N + c],     acc[mt][nt][2]);
                atomicAdd(&Cg[(size_t)(r+8)*N + c + 1], acc[mt][nt][3]);
            } else {
                float b0 = bias[c], b1 = bias[c + 1];
                float v0 = acc[mt][nt][0] + b0, v1 = acc[mt][nt][1] + b1;
                float v2 = acc[mt][nt][2] + b0, v3 = acc[mt][nt][3] + b1;
                if constexpr (EPI == EPI_RELU) {
                    v0 = fmaxf(v0, 0.f); v1 = fmaxf(v1, 0.f);
                    v2 = fmaxf(v2, 0.f); v3 = fmaxf(v3, 0.f);
                }
                if constexpr (EPI == EPI_ADD) {
                    float2 rl = *(const float2*)&resid[(size_t)r*N + c];
                    float2 rh = *(const float2*)&resid[(size_t)(r+8)*N + c];
                    v0 += rl.x; v1 += rl.y; v2 += rh.x; v3 += rh.y;
                }
                *(float2*)&Cg[(size_t)r*N + c]     = make_float2(v0, v1);
                *(float2*)&Cg[(size_t)(r+8)*N + c] = make_float2(v2, v3);
            }
        }
    }
}

// ---------------- row LayerNorm over H=128 (2 rows / 256-thread block) --------
__global__ __launch_bounds__(256) void ln_k(const float* __restrict__ src,
                                            const float* __restrict__ g,
                                            const float* __restrict__ b,
                                            float* __restrict__ dst)
{
    int half = threadIdx.x >> 7;
    int c    = threadIdx.x & 127;
    size_t r = (size_t)blockIdx.x * 2 + half;
    float v = src[r*128 + c];
    __shared__ float red[2][4];
    int w = c >> 5, lane = c & 31;
    float s = v;
#pragma unroll
    for (int off = 16; off; off >>= 1) s += __shfl_xor_sync(0xffffffffu, s, off);
    if (lane == 0) red[half][w] = s;
    __syncthreads();
    float mu = (red[half][0] + red[half][1] + red[half][2] + red[half][3]) * (1.f/128.f);
    __syncthreads();
    float d = v - mu;
    float q = d * d;
#pragma unroll
    for (int off = 16; off; off >>= 1) q += __shfl_xor_sync(0xffffffffu, q, off);
    if (lane == 0) red[half][w] = q;
    __syncthreads();
    float var = (red[half][0] + red[half][1] + red[half][2] + red[half][3]) * (1.f/128.f);
    dst[r*128 + c] = d * rsqrtf(var + 1e-5f) * g[c] + b[c];
}

// ---------------- attention: K/V in registers, broadcast q and p --------------
// 8 warps per forest: warp w -> head = w&3, query group = w>>2 (21 queries).
// Lane j caches K rows j and j+32 (head slice) and V column element V[*][hc+lane].
__global__ __launch_bounds__(256) void attn_k(const float* __restrict__ qkv,
                                              float* __restrict__ o)
{
    int fb = blockIdx.x;
    __shared__ float pr[8][44];

    int tid  = threadIdx.x;
    int warp = tid >> 5, lane = tid & 31;
    int h   = warp & 3;
    int grp = warp >> 2;
    int hc  = h * HD;
    size_t base = (size_t)fb * NN * (3*H);

    // ---- cache K rows (lane = key) ----
    float k0[HD], k1[HD];
    {
        const float4* kr = (const float4*)&qkv[base + (size_t)lane*(3*H) + H + hc];
#pragma unroll
        for (int c4 = 0; c4 < HD/4; c4++) {
            float4 t = kr[c4];
            k0[c4*4+0] = t.x; k0[c4*4+1] = t.y; k0[c4*4+2] = t.z; k0[c4*4+3] = t.w;
        }
    }
    if (lane < NN - 32) {
        const float4* kr = (const float4*)&qkv[base + (size_t)(lane+32)*(3*H) + H + hc];
#pragma unroll
        for (int c4 = 0; c4 < HD/4; c4++) {
            float4 t = kr[c4];
            k1[c4*4+0] = t.x; k1[c4*4+1] = t.y; k1[c4*4+2] = t.z; k1[c4*4+3] = t.w;
        }
    } else {
#pragma unroll
        for (int d = 0; d < HD; d++) k1[d] = 0.f;
    }

    // ---- cache V column (lane = output dim hc+lane... lane spans 32 = HD) ----
    float v[NN];
#pragma unroll
    for (int j = 0; j < NN; j++)
        v[j] = qkv[base + (size_t)j*(3*H) + 2*H + hc + lane];

    const float scale = 0.17677669529663687f;   // 1/sqrt(32)
    int i0 = grp * 21, i1 = i0 + 21;

    for (int i = i0; i < i1; i++) {
        const float4* qp = (const float4*)&qkv[base + (size_t)i*(3*H) + hc];
        float a0 = 0.f, a1 = 0.f;
#pragma unroll
        for (int c4 = 0; c4 < HD/4; c4++) {
            float4 q4 = qp[c4];      // broadcast load
            a0 += q4.x*k0[c4*4+0] + q4.y*k0[c4*4+1] + q4.z*k0[c4*4+2] + q4.w*k0[c4*4+3];
            a1 += q4.x*k1[c4*4+0] + q4.y*k1[c4*4+1] + q4.z*k1[c4*4+2] + q4.w*k1[c4*4+3];
        }
        float s0 = a0 * scale;
        float s1 = (lane < NN - 32) ? a1 * scale : -1e30f;

        float m = fmaxf(s0, s1);
#pragma unroll
        for (int off = 16; off; off >>= 1) m = fmaxf(m, __shfl_xor_sync(0xffffffffu, m, off));
        float p0 = __expf(s0 - m);
        float p1 = (lane < NN - 32) ? __expf(s1 - m) : 0.f;
        float sum = p0 + p1;
#pragma unroll
        for (int off = 16; off; off >>= 1) sum += __shfl_xor_sync(0xffffffffu, sum, off);
        float inv = 1.f / sum;
        pr[warp][lane] = p0 * inv;
        if (lane < NN - 32) pr[warp][lane + 32] = p1 * inv;
        __syncwarp();

        float acc = 0.f;
        const float4* p4 = (const float4*)pr[warp];
#pragma unroll
        for (int c = 0; c < 10; c++) {
            float4 p = p4[c];        // broadcast LDS.128
            acc += p.x*v[c*4+0] + p.y*v[c*4+1] + p.z*v[c*4+2] + p.w*v[c*4+3];
        }
        {
            float4 p = p4[10];
            acc += p.x*v[40] + p.y*v[41];
        }
        o[((size_t)(fb*NN + i))*H + hc + lane] = acc;
        __syncwarp();
    }
}

// ---------------- final LN over OUT=128 ----------------
__global__ __launch_bounds__(128) void lnf_k(const float* __restrict__ fin,
                                             const float* __restrict__ bo,
                                             const float* __restrict__ g,
                                             const float* __restrict__ b,
                                             float* __restrict__ out)
{
    int r = blockIdx.x, c = threadIdx.x;
    float v = fin[(size_t)r*OUTD + c] + bo[c];
    __shared__ float red[4];
    float s = v;
#pragma unroll
    for (int off = 16; off; off >>= 1) s += __shfl_xor_sync(0xffffffffu, s, off);
    if ((c & 31) == 0) red[c >> 5] = s;
    __syncthreads();
    float mu = (red[0] + red[1] + red[2] + red[3]) * (1.f/128.f);
    __syncthreads();
    float d = v - mu;
    float q = d * d;
#pragma unroll
    for (int off = 16; off; off >>= 1) q += __shfl_xor_sync(0xffffffffu, q, off);
    if ((c & 31) == 0) red[c >> 5] = q;
    __syncthreads();
    float var = (red[0] + red[1] + red[2] + red[3]) * (1.f/128.f);
    float rs = rsqrtf(var + 1e-5f);
    out[(size_t)r*OUTD + c] = d * rs * g[c] + b[c];
}

// ---------------- launch ----------------
extern "C" void kernel_launch(void* const* d_in, const int* in_sizes, int n_in,
                              void* d_out, int out_size)
{
    const float* forest = (const float*)d_in[0];
    const int*   adj    = (const int*)  d_in[1];
    const int*   order  = (const int*)  d_in[2];
    const float* W_in   = (const float*)d_in[3];
    const float* b_in   = (const float*)d_in[4];
    const float* qkv_w  = (const float*)d_in[5];
    const float* qkv_b  = (const float*)d_in[6];
    const float* aow    = (const float*)d_in[7];
    const float* aob    = (const float*)d_in[8];
    const float* f1w    = (const float*)d_in[9];
    const float* f1b    = (const float*)d_in[10];
    const float* f2w    = (const float*)d_in[11];
    const float* f2b    = (const float*)d_in[12];
    const float* ln1g   = (const float*)d_in[13];
    const float* ln1b   = (const float*)d_in[14];
    const float* ln2g   = (const float*)d_in[15];
    const float* ln2b   = (const float*)d_in[16];
    const float* Wout   = (const float*)d_in[17];
    const float* bout   = (const float*)d_in[18];
    const float* lnfg   = (const float*)d_in[19];
    const float* lnfb   = (const float*)d_in[20];

    float *px, *ppos, *pqkv, *pfin;
    cudaGetSymbolAddress((void**)&px,   g_x);
    cudaGetSymbolAddress((void**)&ppos, g_pos);
    cudaGetSymbolAddress((void**)&pqkv, g_qkv);
    cudaGetSymbolAddress((void**)&pfin, g_fin);

    // 1) positional encoding
    pos_kernel<<<FB, 128>>>(adj, order, ppos);

    // 2) embed: x = forest @ W_in^T + b_in + pos
    gemm_tc<EPI_ADD><<<dim3(TT/BM, 1, 1), 256>>>(
        forest, W_in, b_in, ppos, px, TT, H, NIN);

    for (int l = 0; l < LL; l++) {
        // qkv = x @ qkv_w^T + b    (N = 384)
        gemm_tc<EPI_BIAS><<<dim3(TT/BM, 3, 1), 256>>>(
            px, qkv_w + (size_t)l*3*H*H, qkv_b + (size_t)l*3*H,
            nullptr, pqkv, TT, 3*H, H);
        // attention -> ppos
        attn_k<<<FB, 256>>>(pqkv, ppos);
        // t = attn_out @ aow^T + aob + x  -> pqkv ; then LN -> x
        gemm_tc<EPI_ADD><<<dim3(TT/BM, 1, 1), 256>>>(
            ppos, aow + (size_t)l*H*H, aob + (size_t)l*H, px, pqkv, TT, H, H);
        ln_k<<<TT/2, 256>>>(pqkv, ln1g + (size_t)l*H, ln1b + (size_t)l*H, px);
        // ff hidden = relu(x @ f1w^T + f1b)  -> pqkv (N = 256)
        gemm_tc<EPI_RELU><<<dim3(TT/BM, 2, 1), 256>>>(
            px, f1w + (size_t)l*FF*H, f1b + (size_t)l*FF, nullptr, pqkv, TT, FF, H);
        // t = hidden @ f2w^T + f2b + x -> ppos ; then LN -> x
        gemm_tc<EPI_ADD><<<dim3(TT/BM, 1, 1), 256>>>(
            pqkv, f2w + (size_t)l*H*FF, f2b + (size_t)l*H, px, ppos, TT, H, FF);
        ln_k<<<TT/2, 256>>>(ppos, ln2g + (size_t)l*H, ln2b + (size_t)l*H, px);
    }

    // 3) final: out = LN( x.reshape(FB, NN*H) @ Wout^T + b_out )
    cudaMemsetAsync(pfin, 0, (size_t)FB*OUTD*sizeof(float));
    gemm_tc<EPI_ATOMIC><<<dim3(FB/BM, 1, 8), 256>>>(
        px, Wout, nullptr, nullptr, pfin, FB, OUTD, NN*H);
    lnf_k<<<FB, 128>>>(pfin, bout, lnfg, lnfb, (float*)d_out);
}

// round 10
// speedup vs baseline: 1.7519x; 1.7519x over previous
#include <cuda_runtime.h>
#include <cuda_bf16.h>
#include <math.h>

// ---------------- problem constants ----------------
#define B_    512
#define A_    8
#define NN    42
#define NIN   32
#define H     128
#define BFN   3
#define NH    4
#define LL    2
#define FF    256
#define OUTD  128
#define EE    41
#define HD    32
#define FB    (B_*A_)        // 4096
#define TT    (FB*NN)        // 172032

// ---------------- scratch (no allocs allowed) ----------------
__device__ float g_x[(size_t)TT*H];
__device__ float g_pos[(size_t)TT*H];
__device__ float g_qkv[(size_t)TT*3*H];
__device__ float g_fin[(size_t)FB*OUTD];

// ---------------- positional encoding (single topological pass) ----------------
// Edge e has child = e+1 and parent <= e, so edge order is topological.
__global__ __launch_bounds__(128) void pos_kernel(const int* __restrict__ adj,
                                                  const int* __restrict__ order,
                                                  float* __restrict__ pos)
{
    int fb = blockIdx.x;
    int h  = threadIdx.x;    // 0..127  (owns column h for all nodes)
    __shared__ int   par[EE];
    __shared__ int   eidx[EE];
    __shared__ int   dep[NN];
    __shared__ float ps[NN][H];

    if (h < EE) {
        const int* e = &adj[((size_t)fb*EE + h)*3];
        par[h] = e[0] - fb*NN;
        int s = e[2] + 1; s = min(max(s, 0), BFN-1);
        eidx[h] = s;
    }
    __syncthreads();
    if (h == 0) {
        dep[0] = 0;
        for (int e = 0; e < EE; e++) {
            int p  = par[e];
            int dp = dep[p];
            dep[e + 1] = dp + 1;
            eidx[e] = dp * BFN + eidx[e];
        }
    }
    ps[0][h] = 0.f;
    __syncthreads();

#pragma unroll 1
    for (int e = 0; e < EE; e++) {
        float v = ps[par[e]][h] + ((h == eidx[e]) ? 1.f : 0.f);
        ps[e + 1][h] = v;
    }
    for (int n = 0; n < NN; n++)
        pos[((size_t)(fb*NN + n))*H + h] = ps[n][h];
}

// ---------------- TF32 tensor-core GEMM  C = A[M,K] @ W[N,K]^T ----------------
__device__ __forceinline__ unsigned f2tf(float f)
{
    unsigned u;
    asm("cvt.rna.tf32.f32 %0, %1;" : "=r"(u) : "f"(f));
    return u;
}

#define BM  128
#define BN  128
#define BK  16
#define LDK 20

#define EPI_BIAS   0
#define EPI_RELU   1
#define EPI_ADD    2
#define EPI_ATOMIC 3
#define EPI_LN     4     // bias + resid + row LayerNorm (requires N==128, grid.y==1, grid.z==1)

template<int EPI>
__global__ __launch_bounds__(256)
void gemm_tc(const float* __restrict__ Ag, const float* __restrict__ Wg,
             const float* __restrict__ bias, const float* __restrict__ resid,
             const float* __restrict__ gam,  const float* __restrict__ bet,
             float* __restrict__ Cg, int M, int N, int K)
{
    __shared__ unsigned As[2][BM][LDK];
    __shared__ unsigned Bs[2][BN][LDK];

    int m0 = blockIdx.x * BM;
    int n0 = blockIdx.y * BN;
    int per = K / gridDim.z;
    int ks  = blockIdx.z * per;
    int ke  = ks + per;

    int tid  = threadIdx.x;
    int lane = tid & 31;
    int warp = tid >> 5;
    int wm = warp >> 2;
    int wn = warp & 3;
    int gid = lane >> 2;
    int tg  = lane & 3;
    int lrow = tid >> 1;
    int lcol = (tid & 1) * 8;

    float acc[4][4][4];
#pragma unroll
    for (int i = 0; i < 4; i++)
#pragma unroll
        for (int j = 0; j < 4; j++)
#pragma unroll
            for (int k = 0; k < 4; k++) acc[i][j][k] = 0.f;

    const float* Ap = Ag + (size_t)(m0 + lrow) * K + lcol;
    const float* Wp = Wg + (size_t)(n0 + lrow) * K + lcol;

    float4 av0, av1, wv0, wv1;

    av0 = *(const float4*)(Ap + ks);
    av1 = *(const float4*)(Ap + ks + 4);
    wv0 = *(const float4*)(Wp + ks);
    wv1 = *(const float4*)(Wp + ks + 4);
    *(uint4*)&As[0][lrow][lcol]     = make_uint4(f2tf(av0.x), f2tf(av0.y), f2tf(av0.z), f2tf(av0.w));
    *(uint4*)&As[0][lrow][lcol + 4] = make_uint4(f2tf(av1.x), f2tf(av1.y), f2tf(av1.z), f2tf(av1.w));
    *(uint4*)&Bs[0][lrow][lcol]     = make_uint4(f2tf(wv0.x), f2tf(wv0.y), f2tf(wv0.z), f2tf(wv0.w));
    *(uint4*)&Bs[0][lrow][lcol + 4] = make_uint4(f2tf(wv1.x), f2tf(wv1.y), f2tf(wv1.z), f2tf(wv1.w));
    __syncthreads();

    int cur = 0;
    for (int kt = ks; kt < ke; kt += BK) {
        bool more = (kt + BK) < ke;
        if (more) {
            av0 = *(const float4*)(Ap + kt + BK);
            av1 = *(const float4*)(Ap + kt + BK + 4);
            wv0 = *(const float4*)(Wp + kt + BK);
            wv1 = *(const float4*)(Wp + kt + BK + 4);
        }

#pragma unroll
        for (int k2 = 0; k2 < 2; k2++) {
            int kk = k2 * 8;
            unsigned af[4][4], bf[4][2];
#pragma unroll
            for (int mt = 0; mt < 4; mt++) {
                int r = wm*64 + mt*16 + gid;
                af[mt][0] = As[cur][r    ][kk + tg];
                af[mt][1] = As[cur][r + 8][kk + tg];
                af[mt][2] = As[cur][r    ][kk + tg + 4];
                af[mt][3] = As[cur][r + 8][kk + tg + 4];
            }
#pragma unroll
            for (int nt = 0; nt < 4; nt++) {
                int c = wn*32 + nt*8 + gid;
                bf[nt][0] = Bs[cur][c][kk + tg];
                bf[nt][1] = Bs[cur][c][kk + tg + 4];
            }
#pragma unroll
            for (int mt = 0; mt < 4; mt++)
#pragma unroll
                for (int nt = 0; nt < 4; nt++) {
                    asm volatile(
                        "mma.sync.aligned.m16n8k8.row.col.f32.tf32.tf32.f32 "
                        "{%0,%1,%2,%3}, {%4,%5,%6,%7}, {%8,%9}, {%0,%1,%2,%3};\n"
                        : "+f"(acc[mt][nt][0]), "+f"(acc[mt][nt][1]),
                          "+f"(acc[mt][nt][2]), "+f"(acc[mt][nt][3])
                        : "r"(af[mt][0]), "r"(af[mt][1]), "r"(af[mt][2]), "r"(af[mt][3]),
                          "r"(bf[nt][0]), "r"(bf[nt][1]));
                }
        }

        if (more) {
            int nxt = cur ^ 1;
            *(uint4*)&As[nxt][lrow][lcol]     = make_uint4(f2tf(av0.x), f2tf(av0.y), f2tf(av0.z), f2tf(av0.w));
            *(uint4*)&As[nxt][lrow][lcol + 4] = make_uint4(f2tf(av1.x), f2tf(av1.y), f2tf(av1.z), f2tf(av1.w));
            *(uint4*)&Bs[nxt][lrow][lcol]     = make_uint4(f2tf(wv0.x), f2tf(wv0.y), f2tf(wv0.z), f2tf(wv0.w));
            *(uint4*)&Bs[nxt][lrow][lcol + 4] = make_uint4(f2tf(wv1.x), f2tf(wv1.y), f2tf(wv1.z), f2tf(wv1.w));
            __syncthreads();
        }
        cur ^= 1;
    }

    if constexpr (EPI == EPI_LN) {
        // bias + resid into acc, then block-wide row LayerNorm (N == 128)
        __shared__ float red1[BM][4];
        __shared__ float red2[BM][4];
        float mu0[4], mu1[4];

#pragma unroll
        for (int mt = 0; mt < 4; mt++) {
            int r = m0 + wm*64 + mt*16 + gid;
            float s0 = 0.f, s1 = 0.f;
#pragma unroll
            for (int nt = 0; nt < 4; nt++) {
                int c = wn*32 + nt*8 + 2*tg;
                float b0 = bias[c], b1 = bias[c + 1];
                float2 rl = *(const float2*)&resid[(size_t)r*128 + c];
                float2 rh = *(const float2*)&resid[(size_t)(r+8)*128 + c];
                acc[mt][nt][0] += b0 + rl.x;
                acc[mt][nt][1] += b1 + rl.y;
                acc[mt][nt][2] += b0 + rh.x;
                acc[mt][nt][3] += b1 + rh.y;
                s0 += acc[mt][nt][0] + acc[mt][nt][1];
                s1 += acc[mt][nt][2] + acc[mt][nt][3];
            }
            s0 += __shfl_xor_sync(0xffffffffu, s0, 1);
            s0 += __shfl_xor_sync(0xffffffffu, s0, 2);
            s1 += __shfl_xor_sync(0xffffffffu, s1, 1);
            s1 += __shfl_xor_sync(0xffffffffu, s1, 2);
            if (tg == 0) {
                red1[wm*64 + mt*16 + gid    ][wn] = s0;
                red1[wm*64 + mt*16 + gid + 8][wn] = s1;
            }
        }
        __syncthreads();
#pragma unroll
        for (int mt = 0; mt < 4; mt++) {
            int rl_ = wm*64 + mt*16 + gid;
            mu0[mt] = (red1[rl_    ][0] + red1[rl_    ][1] + red1[rl_    ][2] + red1[rl_    ][3]) * (1.f/128.f);
            mu1[mt] = (red1[rl_ + 8][0] + red1[rl_ + 8][1] + red1[rl_ + 8][2] + red1[rl_ + 8][3]) * (1.f/128.f);
            float q0 = 0.f, q1 = 0.f;
#pragma unroll
            for (int nt = 0; nt < 4; nt++) {
                float d0 = acc[mt][nt][0] - mu0[mt];
                float d1 = acc[mt][nt][1] - mu0[mt];
                float d2 = acc[mt][nt][2] - mu1[mt];
                float d3 = acc[mt][nt][3] - mu1[mt];
                q0 += d0*d0 + d1*d1;
                q1 += d2*d2 + d3*d3;
            }
            q0 += __shfl_xor_sync(0xffffffffu, q0, 1);
            q0 += __shfl_xor_sync(0xffffffffu, q0, 2);
            q1 += __shfl_xor_sync(0xffffffffu, q1, 1);
            q1 += __shfl_xor_sync(0xffffffffu, q1, 2);
            if (tg == 0) {
                red2[rl_    ][wn] = q0;
                red2[rl_ + 8][wn] = q1;
            }
        }
        __syncthreads();
#pragma unroll
        for (int mt = 0; mt < 4; mt++) {
            int rl_ = wm*64 + mt*16 + gid;
            int r = m0 + rl_;
            float rs0 = rsqrtf((red2[rl_    ][0] + red2[rl_    ][1] + red2[rl_    ][2] + red2[rl_    ][3]) * (1.f/128.f) + 1e-5f);
            float rs1 = rsqrtf((red2[rl_ + 8][0] + red2[rl_ + 8][1] + red2[rl_ + 8][2] + red2[rl_ + 8][3]) * (1.f/128.f) + 1e-5f);
#pragma unroll
            for (int nt = 0; nt < 4; nt++) {
                int c = wn*32 + nt*8 + 2*tg;
                float g0 = gam[c], g1 = gam[c + 1];
                float e0 = bet[c], e1 = bet[c + 1];
                float v0 = (acc[mt][nt][0] - mu0[mt]) * rs0 * g0 + e0;
                float v1 = (acc[mt][nt][1] - mu0[mt]) * rs0 * g1 + e1;
                float v2 = (acc[mt][nt][2] - mu1[mt]) * rs1 * g0 + e0;
                float v3 = (acc[mt][nt][3] - mu1[mt]) * rs1 * g1 + e1;
                *(float2*)&Cg[(size_t)r*128 + c]     = make_float2(v0, v1);
                *(float2*)&Cg[(size_t)(r+8)*128 + c] = make_float2(v2, v3);
            }
        }
    } else {
#pragma unroll
        for (int mt = 0; mt < 4; mt++) {
#pragma unroll
            for (int nt = 0; nt < 4; nt++) {
                int r = m0 + wm*64 + mt*16 + gid;
                int c = n0 + wn*32 + nt*8 + 2*tg;
                if constexpr (EPI == EPI_ATOMIC) {
                    atomicAdd(&Cg[(size_t)r*N + c],         acc[mt][nt][0]);
                    atomicAdd(&Cg[(size_t)r*N + c + 1],     acc[mt][nt][1]);
                    atomicAdd(&Cg[(size_t)(r+8)*N + c],     acc[mt][nt][2]);
                    atomicAdd(&Cg[(size_t)(r+8)*N + c + 1], acc[mt][nt][3]);
                } else {
                    float b0 = bias[c], b1 = bias[c + 1];
                    float v0 = acc[mt][nt][0] + b0, v1 = acc[mt][nt][1] + b1;
                    float v2 = acc[mt][nt][2] + b0, v3 = acc[mt][nt][3] + b1;
                    if constexpr (EPI == EPI_RELU) {
                        v0 = fmaxf(v0, 0.f); v1 = fmaxf(v1, 0.f);
                        v2 = fmaxf(v2, 0.f); v3 = fmaxf(v3, 0.f);
                    }
                    if constexpr (EPI == EPI_ADD) {
                        float2 rl = *(const float2*)&resid[(size_t)r*N + c];
                        float2 rh = *(const float2*)&resid[(size_t)(r+8)*N + c];
                        v0 += rl.x; v1 += rl.y; v2 += rh.x; v3 += rh.y;
                    }
                    *(float2*)&Cg[(size_t)r*N + c]     = make_float2(v0, v1);
                    *(float2*)&Cg[(size_t)(r+8)*N + c] = make_float2(v2, v3);
                }
            }
        }
    }
}

// ---------------- attention: smem K + transposed V, 8 warps / forest ---------
// warp w: head = w&3, query-group = w>>2 (21 queries each).
#define KSP 132  // K row stride (words): 16B-aligned rows, conflict-free LDS.128
#define VTP 44   // vt row stride (words): 16B-aligned rows, conflict-free LDS.128

__global__ __launch_bounds__(256) void attn_k(const float* __restrict__ qkv,
                                              float* __restrict__ o)
{
    int fb = blockIdx.x;
    __shared__ float ks_[NN][KSP];     // [key][dim]
    __shared__ float vt[H][VTP];       // [dim][key]  (transposed V)
    __shared__ float pr[8][VTP];

    int tid = threadIdx.x;
    size_t base = (size_t)fb * NN * (3*H);
    for (int idx = tid; idx < NN*H; idx += 256) {
        int n = idx >> 7, c = idx & 127;
        const float* row = &qkv[base + (size_t)n*(3*H)];
        ks_[n][c] = row[H + c];
        vt[c][n]  = row[2*H + c];
    }
    __syncthreads();

    int warp = tid >> 5, lane = tid & 31;
    int h   = warp & 3;
    int grp = warp >> 2;
    int hc  = h * HD;
    int i0  = grp * 21;
    int i1  = i0 + 21;

    const float scale = 0.17677669529663687f;   // 1/sqrt(32)
    const float* vrow = vt[hc + lane];

    for (int i = i0; i < i1; i++) {
        const float4* qp = (const float4*)&qkv[base + (size_t)i*(3*H) + hc];
        float a0 = 0.f, a1 = 0.f;
#pragma unroll
        for (int c4 = 0; c4 < HD/4; c4++) {
            float4 q4 = qp[c4];                                // broadcast LDG
            float4 kA = *(const float4*)&ks_[lane][hc + c4*4]; // LDS.128, 16B-aligned
            a0 += q4.x*kA.x + q4.y*kA.y + q4.z*kA.z + q4.w*kA.w;
            if (lane < NN - 32) {
                float4 kB = *(const float4*)&ks_[lane + 32][hc + c4*4];
                a1 += q4.x*kB.x + q4.y*kB.y + q4.z*kB.z + q4.w*kB.w;
            }
        }
        float s0 = a0 * scale;
        float s1 = (lane < NN - 32) ? a1 * scale : -1e30f;

        float m = fmaxf(s0, s1);
#pragma unroll
        for (int off = 16; off; off >>= 1) m = fmaxf(m, __shfl_xor_sync(0xffffffffu, m, off));
        float p0 = __expf(s0 - m);
        float p1 = (lane < NN - 32) ? __expf(s1 - m) : 0.f;
        float sum = p0 + p1;
#pragma unroll
        for (int off = 16; off; off >>= 1) sum += __shfl_xor_sync(0xffffffffu, sum, off);
        float inv = 1.f / sum;
        pr[warp][lane] = p0 * inv;
        if (lane < NN - 32) pr[warp][lane + 32] = p1 * inv;
        __syncwarp();

        float acc = 0.f;
        const float4* p4 = (const float4*)pr[warp];
        const float4* v4 = (const float4*)vrow;
#pragma unroll
        for (int c = 0; c < 10; c++) {
            float4 p = p4[c];     // broadcast LDS.128
            float4 v = v4[c];     // LDS.128, conflict-free
            acc += p.x*v.x + p.y*v.y + p.z*v.z + p.w*v.w;
        }
        {
            float2 p = *(const float2*)&pr[warp][40];
            float2 v = *(const float2*)&vrow[40];
            acc += p.x*v.x + p.y*v.y;
        }
        o[((size_t)(fb*NN + i))*H + hc + lane] = acc;
        __syncwarp();
    }
}

// ---------------- final LN over OUT=128 ----------------
__global__ __launch_bounds__(128) void lnf_k(const float* __restrict__ fin,
                                             const float* __restrict__ bo,
                                             const float* __restrict__ g,
                                             const float* __restrict__ b,
                                             float* __restrict__ out)
{
    int r = blockIdx.x, c = threadIdx.x;
    float v = fin[(size_t)r*OUTD + c] + bo[c];
    __shared__ float red[4];
    float s = v;
#pragma unroll
    for (int off = 16; off; off >>= 1) s += __shfl_xor_sync(0xffffffffu, s, off);
    if ((c & 31) == 0) red[c >> 5] = s;
    __syncthreads();
    float mu = (red[0] + red[1] + red[2] + red[3]) * (1.f/128.f);
    __syncthreads();
    float d = v - mu;
    float q = d * d;
#pragma unroll
    for (int off = 16; off; off >>= 1) q += __shfl_xor_sync(0xffffffffu, q, off);
    if ((c & 31) == 0) red[c >> 5] = q;
    __syncthreads();
    float var = (red[0] + red[1] + red[2] + red[3]) * (1.f/128.f);
    float rs = rsqrtf(var + 1e-5f);
    out[(size_t)r*OUTD + c] = d * rs * g[c] + b[c];
}

// ---------------- launch ----------------
extern "C" void kernel_launch(void* const* d_in, const int* in_sizes, int n_in,
                              void* d_out, int out_size)
{
    const float* forest = (const float*)d_in[0];
    const int*   adj    = (const int*)  d_in[1];
    const int*   order  = (const int*)  d_in[2];
    const float* W_in   = (const float*)d_in[3];
    const float* b_in   = (const float*)d_in[4];
    const float* qkv_w  = (const float*)d_in[5];
    const float* qkv_b  = (const float*)d_in[6];
    const float* aow    = (const float*)d_in[7];
    const float* aob    = (const float*)d_in[8];
    const float* f1w    = (const float*)d_in[9];
    const float* f1b    = (const float*)d_in[10];
    const float* f2w    = (const float*)d_in[11];
    const float* f2b    = (const float*)d_in[12];
    const float* ln1g   = (const float*)d_in[13];
    const float* ln1b   = (const float*)d_in[14];
    const float* ln2g   = (const float*)d_in[15];
    const float* ln2b   = (const float*)d_in[16];
    const float* Wout   = (const float*)d_in[17];
    const float* bout   = (const float*)d_in[18];
    const float* lnfg   = (const float*)d_in[19];
    const float* lnfb   = (const float*)d_in[20];

    float *px, *ppos, *pqkv, *pfin;
    cudaGetSymbolAddress((void**)&px,   g_x);
    cudaGetSymbolAddress((void**)&ppos, g_pos);
    cudaGetSymbolAddress((void**)&pqkv, g_qkv);
    cudaGetSymbolAddress((void**)&pfin, g_fin);

    // 1) positional encoding
    pos_kernel<<<FB, 128>>>(adj, order, ppos);

    // 2) embed: x = forest @ W_in^T + b_in + pos
    gemm_tc<EPI_ADD><<<dim3(TT/BM, 1, 1), 256>>>(
        forest, W_in, b_in, ppos, nullptr, nullptr, px, TT, H, NIN);

    for (int l = 0; l < LL; l++) {
        // qkv = x @ qkv_w^T + b    (N = 384)
        gemm_tc<EPI_BIAS><<<dim3(TT/BM, 3, 1), 256>>>(
            px, qkv_w + (size_t)l*3*H*H, qkv_b + (size_t)l*3*H,
            nullptr, nullptr, nullptr, pqkv, TT, 3*H, H);
        // attention -> ppos
        attn_k<<<FB, 256>>>(pqkv, ppos);
        // x = LN( attn_out @ aow^T + aob + x )   (fused epilogue)
        gemm_tc<EPI_LN><<<dim3(TT/BM, 1, 1), 256>>>(
            ppos, aow + (size_t)l*H*H, aob + (size_t)l*H, px,
            ln1g + (size_t)l*H, ln1b + (size_t)l*H, px, TT, H, H);
        // hidden = relu(x @ f1w^T + f1b)  (N = 256)
        gemm_tc<EPI_RELU><<<dim3(TT/BM, 2, 1), 256>>>(
            px, f1w + (size_t)l*FF*H, f1b + (size_t)l*FF,
            nullptr, nullptr, nullptr, pqkv, TT, FF, H);
        // x = LN( hidden @ f2w^T + f2b + x )     (fused epilogue)
        gemm_tc<EPI_LN><<<dim3(TT/BM, 1, 1), 256>>>(
            pqkv, f2w + (size_t)l*H*FF, f2b + (size_t)l*H, px,
            ln2g + (size_t)l*H, ln2b + (size_t)l*H, px, TT, H, FF);
    }

    // 3) final: out = LN( x.reshape(FB, NN*H) @ Wout^T + b_out )
    cudaMemsetAsync(pfin, 0, (size_t)FB*OUTD*sizeof(float));
    gemm_tc<EPI_ATOMIC><<<dim3(FB/BM, 1, 8), 256>>>(
        px, Wout, nullptr, nullptr, nullptr, nullptr, pfin, FB, OUTD, NN*H);
    lnf_k<<<FB, 128>>>(pfin, bout, lnfg, lnfb, (float*)d_out);
}

// round 12
// speedup vs baseline: 2.1447x; 1.2242x over previous
#include <cuda_runtime.h>
#include <cuda_bf16.h>
#include <math.h>

// ---------------- problem constants ----------------
#define B_    512
#define A_    8
#define NN    42
#define NIN   32
#define H     128
#define BFN   3
#define NH    4
#define LL    2
#define FF    256
#define OUTD  128
#define EE    41
#define HD    32
#define FB    (B_*A_)        // 4096
#define TT    (FB*NN)        // 172032

// ---------------- scratch (no allocs allowed) ----------------
__device__ float g_x[(size_t)TT*H];
__device__ float g_pos[(size_t)TT*H];
__device__ float g_qkv[(size_t)TT*3*H];
__device__ float g_fin[(size_t)FB*OUTD];

// ---------------- positional encoding (single topological pass) ----------------
__global__ __launch_bounds__(128) void pos_kernel(const int* __restrict__ adj,
                                                  const int* __restrict__ order,
                                                  float* __restrict__ pos)
{
    int fb = blockIdx.x;
    int h  = threadIdx.x;
    __shared__ int   par[EE];
    __shared__ int   eidx[EE];
    __shared__ int   dep[NN];
    __shared__ float ps[NN][H];

    if (h < EE) {
        const int* e = &adj[((size_t)fb*EE + h)*3];
        par[h] = e[0] - fb*NN;
        int s = e[2] + 1; s = min(max(s, 0), BFN-1);
        eidx[h] = s;
    }
    __syncthreads();
    if (h == 0) {
        dep[0] = 0;
        for (int e = 0; e < EE; e++) {
            int p  = par[e];
            int dp = dep[p];
            dep[e + 1] = dp + 1;
            eidx[e] = dp * BFN + eidx[e];
        }
    }
    ps[0][h] = 0.f;
    __syncthreads();

#pragma unroll 1
    for (int e = 0; e < EE; e++) {
        float v = ps[par[e]][h] + ((h == eidx[e]) ? 1.f : 0.f);
        ps[e + 1][h] = v;
    }
    for (int n = 0; n < NN; n++)
        pos[((size_t)(fb*NN + n))*H + h] = ps[n][h];
}

// ---------------- helpers ----------------
__device__ __forceinline__ unsigned f2tf(float f)
{
    unsigned u;
    asm("cvt.rna.tf32.f32 %0, %1;" : "=r"(u) : "f"(f));
    return u;
}

__device__ __forceinline__ void mma_tf32(float* d, const unsigned* a, const unsigned* b)
{
    asm volatile("mma.sync.aligned.m16n8k8.row.col.f32.tf32.tf32.f32 "
                 "{%0,%1,%2,%3}, {%4,%5,%6,%7}, {%8,%9}, {%0,%1,%2,%3};\n"
                 : "+f"(d[0]), "+f"(d[1]), "+f"(d[2]), "+f"(d[3])
                 : "r"(a[0]), "r"(a[1]), "r"(a[2]), "r"(a[3]),
                   "r"(b[0]), "r"(b[1]));
}

// ---------------- TF32 tensor-core GEMM  C = A[M,K] @ W[N,K]^T ----------------
#define BM  128
#define BN  128
#define BK  16
#define LDK 20

#define EPI_BIAS   0
#define EPI_RELU   1
#define EPI_ADD    2
#define EPI_ATOMIC 3
#define EPI_LN     4

template<int EPI>
__global__ __launch_bounds__(256)
void gemm_tc(const float* __restrict__ Ag, const float* __restrict__ Wg,
             const float* __restrict__ bias, const float* __restrict__ resid,
             const float* __restrict__ gam,  const float* __restrict__ bet,
             float* __restrict__ Cg, int M, int N, int K)
{
    __shared__ unsigned As[2][BM][LDK];
    __shared__ unsigned Bs[2][BN][LDK];

    int m0 = blockIdx.x * BM;
    int n0 = blockIdx.y * BN;
    int per = K / gridDim.z;
    int ks  = blockIdx.z * per;
    int ke  = ks + per;

    int tid  = threadIdx.x;
    int lane = tid & 31;
    int warp = tid >> 5;
    int wm = warp >> 2;
    int wn = warp & 3;
    int gid = lane >> 2;
    int tg  = lane & 3;
    int lrow = tid >> 1;
    int lcol = (tid & 1) * 8;

    float acc[4][4][4];
#pragma unroll
    for (int i = 0; i < 4; i++)
#pragma unroll
        for (int j = 0; j < 4; j++)
#pragma unroll
            for (int k = 0; k < 4; k++) acc[i][j][k] = 0.f;

    const float* Ap = Ag + (size_t)(m0 + lrow) * K + lcol;
    const float* Wp = Wg + (size_t)(n0 + lrow) * K + lcol;

    float4 av0, av1, wv0, wv1;

    av0 = *(const float4*)(Ap + ks);
    av1 = *(const float4*)(Ap + ks + 4);
    wv0 = *(const float4*)(Wp + ks);
    wv1 = *(const float4*)(Wp + ks + 4);
    *(uint4*)&As[0][lrow][lcol]     = make_uint4(f2tf(av0.x), f2tf(av0.y), f2tf(av0.z), f2tf(av0.w));
    *(uint4*)&As[0][lrow][lcol + 4] = make_uint4(f2tf(av1.x), f2tf(av1.y), f2tf(av1.z), f2tf(av1.w));
    *(uint4*)&Bs[0][lrow][lcol]     = make_uint4(f2tf(wv0.x), f2tf(wv0.y), f2tf(wv0.z), f2tf(wv0.w));
    *(uint4*)&Bs[0][lrow][lcol + 4] = make_uint4(f2tf(wv1.x), f2tf(wv1.y), f2tf(wv1.z), f2tf(wv1.w));
    __syncthreads();

    int cur = 0;
    for (int kt = ks; kt < ke; kt += BK) {
        bool more = (kt + BK) < ke;
        if (more) {
            av0 = *(const float4*)(Ap + kt + BK);
            av1 = *(const float4*)(Ap + kt + BK + 4);
            wv0 = *(const float4*)(Wp + kt + BK);
            wv1 = *(const float4*)(Wp + kt + BK + 4);
        }

#pragma unroll
        for (int k2 = 0; k2 < 2; k2++) {
            int kk = k2 * 8;
            unsigned af[4][4], bf[4][2];
#pragma unroll
            for (int mt = 0; mt < 4; mt++) {
                int r = wm*64 + mt*16 + gid;
                af[mt][0] = As[cur][r    ][kk + tg];
                af[mt][1] = As[cur][r + 8][kk + tg];
                af[mt][2] = As[cur][r    ][kk + tg + 4];
                af[mt][3] = As[cur][r + 8][kk + tg + 4];
            }
#pragma unroll
            for (int nt = 0; nt < 4; nt++) {
                int c = wn*32 + nt*8 + gid;
                bf[nt][0] = Bs[cur][c][kk + tg];
                bf[nt][1] = Bs[cur][c][kk + tg + 4];
            }
#pragma unroll
            for (int mt = 0; mt < 4; mt++)
#pragma unroll
                for (int nt = 0; nt < 4; nt++)
                    mma_tf32(acc[mt][nt], af[mt], bf[nt]);
        }

        if (more) {
            int nxt = cur ^ 1;
            *(uint4*)&As[nxt][lrow][lcol]     = make_uint4(f2tf(av0.x), f2tf(av0.y), f2tf(av0.z), f2tf(av0.w));
            *(uint4*)&As[nxt][lrow][lcol + 4] = make_uint4(f2tf(av1.x), f2tf(av1.y), f2tf(av1.z), f2tf(av1.w));
            *(uint4*)&Bs[nxt][lrow][lcol]     = make_uint4(f2tf(wv0.x), f2tf(wv0.y), f2tf(wv0.z), f2tf(wv0.w));
            *(uint4*)&Bs[nxt][lrow][lcol + 4] = make_uint4(f2tf(wv1.x), f2tf(wv1.y), f2tf(wv1.z), f2tf(wv1.w));
            __syncthreads();
        }
        cur ^= 1;
    }

    if constexpr (EPI == EPI_LN) {
        __shared__ float red1[BM][4];
        __shared__ float red2[BM][4];
        float mu0[4], mu1[4];

#pragma unroll
        for (int mt = 0; mt < 4; mt++) {
            int r = m0 + wm*64 + mt*16 + gid;
            float s0 = 0.f, s1 = 0.f;
#pragma unroll
            for (int nt = 0; nt < 4; nt++) {
                int c = wn*32 + nt*8 + 2*tg;
                float b0 = bias[c], b1 = bias[c + 1];
                float2 rl = *(const float2*)&resid[(size_t)r*128 + c];
                float2 rh = *(const float2*)&resid[(size_t)(r+8)*128 + c];
                acc[mt][nt][0] += b0 + rl.x;
                acc[mt][nt][1] += b1 + rl.y;
                acc[mt][nt][2] += b0 + rh.x;
                acc[mt][nt][3] += b1 + rh.y;
                s0 += acc[mt][nt][0] + acc[mt][nt][1];
                s1 += acc[mt][nt][2] + acc[mt][nt][3];
            }
            s0 += __shfl_xor_sync(0xffffffffu, s0, 1);
            s0 += __shfl_xor_sync(0xffffffffu, s0, 2);
            s1 += __shfl_xor_sync(0xffffffffu, s1, 1);
            s1 += __shfl_xor_sync(0xffffffffu, s1, 2);
            if (tg == 0) {
                red1[wm*64 + mt*16 + gid    ][wn] = s0;
                red1[wm*64 + mt*16 + gid + 8][wn] = s1;
            }
        }
        __syncthreads();
#pragma unroll
        for (int mt = 0; mt < 4; mt++) {
            int rl_ = wm*64 + mt*16 + gid;
            mu0[mt] = (red1[rl_    ][0] + red1[rl_    ][1] + red1[rl_    ][2] + red1[rl_    ][3]) * (1.f/128.f);
            mu1[mt] = (red1[rl_ + 8][0] + red1[rl_ + 8][1] + red1[rl_ + 8][2] + red1[rl_ + 8][3]) * (1.f/128.f);
            float q0 = 0.f, q1 = 0.f;
#pragma unroll
            for (int nt = 0; nt < 4; nt++) {
                float d0 = acc[mt][nt][0] - mu0[mt];
                float d1 = acc[mt][nt][1] - mu0[mt];
                float d2 = acc[mt][nt][2] - mu1[mt];
                float d3 = acc[mt][nt][3] - mu1[mt];
                q0 += d0*d0 + d1*d1;
                q1 += d2*d2 + d3*d3;
            }
            q0 += __shfl_xor_sync(0xffffffffu, q0, 1);
            q0 += __shfl_xor_sync(0xffffffffu, q0, 2);
            q1 += __shfl_xor_sync(0xffffffffu, q1, 1);
            q1 += __shfl_xor_sync(0xffffffffu, q1, 2);
            if (tg == 0) {
                red2[rl_    ][wn] = q0;
                red2[rl_ + 8][wn] = q1;
            }
        }
        __syncthreads();
#pragma unroll
        for (int mt = 0; mt < 4; mt++) {
            int rl_ = wm*64 + mt*16 + gid;
            int r = m0 + rl_;
            float rs0 = rsqrtf((red2[rl_    ][0] + red2[rl_    ][1] + red2[rl_    ][2] + red2[rl_    ][3]) * (1.f/128.f) + 1e-5f);
            float rs1 = rsqrtf((red2[rl_ + 8][0] + red2[rl_ + 8][1] + red2[rl_ + 8][2] + red2[rl_ + 8][3]) * (1.f/128.f) + 1e-5f);
#pragma unroll
            for (int nt = 0; nt < 4; nt++) {
                int c = wn*32 + nt*8 + 2*tg;
                float g0 = gam[c], g1 = gam[c + 1];
                float e0 = bet[c], e1 = bet[c + 1];
                float v0 = (acc[mt][nt][0] - mu0[mt]) * rs0 * g0 + e0;
                float v1 = (acc[mt][nt][1] - mu0[mt]) * rs0 * g1 + e1;
                float v2 = (acc[mt][nt][2] - mu1[mt]) * rs1 * g0 + e0;
                float v3 = (acc[mt][nt][3] - mu1[mt]) * rs1 * g1 + e1;
                *(float2*)&Cg[(size_t)r*128 + c]     = make_float2(v0, v1);
                *(float2*)&Cg[(size_t)(r+8)*128 + c] = make_float2(v2, v3);
            }
        }
    } else {
#pragma unroll
        for (int mt = 0; mt < 4; mt++) {
#pragma unroll
            for (int nt = 0; nt < 4; nt++) {
                int r = m0 + wm*64 + mt*16 + gid;
                int c = n0 + wn*32 + nt*8 + 2*tg;
                if constexpr (EPI == EPI_ATOMIC) {
                    atomicAdd(&Cg[(size_t)r*N + c],         acc[mt][nt][0]);
                    atomicAdd(&Cg[(size_t)r*N + c + 1],     acc[mt][nt][1]);
                    atomicAdd(&Cg[(size_t)(r+8)*N + c],     acc[mt][nt][2]);
                    atomicAdd(&Cg[(size_t)(r+8)*N + c + 1], acc[mt][nt][3]);
                } else {
                    float b0 = bias[c], b1 = bias[c + 1];
                    float v0 = acc[mt][nt][0] + b0, v1 = acc[mt][nt][1] + b1;
                    float v2 = acc[mt][nt][2] + b0, v3 = acc[mt][nt][3] + b1;
                    if constexpr (EPI == EPI_RELU) {
                        v0 = fmaxf(v0, 0.f); v1 = fmaxf(v1, 0.f);
                        v2 = fmaxf(v2, 0.f); v3 = fmaxf(v3, 0.f);
                    }
                    if constexpr (EPI == EPI_ADD) {
                        float2 rl = *(const float2*)&resid[(size_t)r*N + c];
                        float2 rh = *(const float2*)&resid[(size_t)(r+8)*N + c];
                        v0 += rl.x; v1 += rl.y; v2 += rh.x; v3 += rh.y;
                    }
                    *(float2*)&Cg[(size_t)r*N + c]     = make_float2(v0, v1);
                    *(float2*)&Cg[(size_t)(r+8)*N + c] = make_float2(v2, v3);
                }
            }
        }
    }
}

// ---------------- tensor-core attention -------------------------------------
// One block per forest (256 thr). warp -> (head = warp>>1, m-half = warp&1).
// S = Q@K^T via mma (M=48 pad, N=48 pad, K=32), softmax in regs (cols>=42
// masked), P stored tf32 into smem overlaying dead Q/K, O = P@V via mma.
#define NP   48
#define QSS  132   // q/k row stride (words)
#define PSS  52    // p / vt row stride (words)
#define ATTN_SMEM_WORDS (2*NP*QSS + H*PSS)   // 12672 + 6656 = 19328
#define ATTN_SMEM_BYTES (ATTN_SMEM_WORDS*4)  // 77312

__global__ __launch_bounds__(256, 2) void attn_k(const float* __restrict__ qkv,
                                                 float* __restrict__ o)
{
    extern __shared__ unsigned sm[];
    unsigned* qs = sm;                 // [48][132]
    unsigned* ks = sm + NP*QSS;        // [48][132]
    unsigned* ps = sm;                 // [4][48][52] overlay (qs+ks dead by then)
    unsigned* vt = sm + 2*NP*QSS;      // [128][52]  V^T

    int fb  = blockIdx.x;
    int tid = threadIdx.x;
    size_t base = (size_t)fb * NN * (3*H);

    for (int idx = tid; idx < NP*H; idx += 256) {
        int n = idx >> 7, c = idx & 127;
        unsigned qv = 0, kv = 0, vv = 0;
        if (n < NN) {
            const float* row = &qkv[base + (size_t)n*(3*H)];
            qv = f2tf(row[c]);
            kv = f2tf(row[H + c]);
            vv = f2tf(row[2*H + c]);
        }
        qs[n*QSS + c] = qv;
        ks[n*QSS + c] = kv;
        vt[c*PSS + n] = vv;
    }
    __syncthreads();

    int warp = tid >> 5, lane = tid & 31;
    int gid = lane >> 2, tg = lane & 3;
    int h     = warp >> 1;
    int grp   = warp & 1;
    int hc    = h * HD;
    int mb    = grp ? 32 : 0;
    int mstep = grp ? 0 : 16;    // grp1 redundantly repeats its single tile (uniform CF)

    // ---- S = Q @ K^T ----
    float acc[2][6][4];
#pragma unroll
    for (int a = 0; a < 2; a++)
#pragma unroll
        for (int b = 0; b < 6; b++)
#pragma unroll
            for (int c = 0; c < 4; c++) acc[a][b][c] = 0.f;

#pragma unroll
    for (int k = 0; k < 4; k++) {
        int kk = hc + k*8;
        unsigned af[2][4], bf[6][2];
#pragma unroll
        for (int mt = 0; mt < 2; mt++) {
            int r = mb + mt*mstep + gid;
            af[mt][0] = qs[r*QSS + kk + tg];
            af[mt][1] = qs[(r+8)*QSS + kk + tg];
            af[mt][2] = qs[r*QSS + kk + tg + 4];
            af[mt][3] = qs[(r+8)*QSS + kk + tg + 4];
        }
#pragma unroll
        for (int nt = 0; nt < 6; nt++) {
            int n = nt*8 + gid;
            bf[nt][0] = ks[n*QSS + kk + tg];
            bf[nt][1] = ks[n*QSS + kk + tg + 4];
        }
#pragma unroll
        for (int mt = 0; mt < 2; mt++)
#pragma unroll
            for (int nt = 0; nt < 6; nt++)
                mma_tf32(acc[mt][nt], af[mt], bf[nt]);
    }
    __syncthreads();   // all reads of qs/ks complete before ps overlay writes

    // ---- softmax (rows live in this warp; cols >= NN masked) + store P ----
    const float scale = 0.17677669529663687f;   // 1/sqrt(32)
    unsigned* psh = ps + h*(NP*PSS);
#pragma unroll
    for (int mt = 0; mt < 2; mt++) {
        int r0 = mb + mt*mstep + gid;
        float m0 = -1e30f, m1 = -1e30f;
#pragma unroll
        for (int nt = 0; nt < 6; nt++) {
            int c0 = nt*8 + 2*tg;
            float v0 = (c0     < NN) ? acc[mt][nt][0]*scale : -1e30f;
            float v1 = (c0 + 1 < NN) ? acc[mt][nt][1]*scale : -1e30f;
            float v2 = (c0     < NN) ? acc[mt][nt][2]*scale : -1e30f;
            float v3 = (c0 + 1 < NN) ? acc[mt][nt][3]*scale : -1e30f;
            acc[mt][nt][0] = v0; acc[mt][nt][1] = v1;
            acc[mt][nt][2] = v2; acc[mt][nt][3] = v3;
            m0 = fmaxf(m0, fmaxf(v0, v1));
            m1 = fmaxf(m1, fmaxf(v2, v3));
        }
        m0 = fmaxf(m0, __shfl_xor_sync(0xffffffffu, m0, 1));
        m0 = fmaxf(m0, __shfl_xor_sync(0xffffffffu, m0, 2));
        m1 = fmaxf(m1, __shfl_xor_sync(0xffffffffu, m1, 1));
        m1 = fmaxf(m1, __shfl_xor_sync(0xffffffffu, m1, 2));
        float s0 = 0.f, s1 = 0.f;
#pragma unroll
        for (int nt = 0; nt < 6; nt++) {
            float p0 = __expf(acc[mt][nt][0] - m0);
            float p1 = __expf(acc[mt][nt][1] - m0);
            float p2 = __expf(acc[mt][nt][2] - m1);
            float p3 = __expf(acc[mt][nt][3] - m1);
            acc[mt][nt][0] = p0; acc[mt][nt][1] = p1;
            acc[mt][nt][2] = p2; acc[mt][nt][3] = p3;
            s0 += p0 + p1; s1 += p2 + p3;
        }
        s0 += __shfl_xor_sync(0xffffffffu, s0, 1);
        s0 += __shfl_xor_sync(0xffffffffu, s0, 2);
        s1 += __shfl_xor_sync(0xffffffffu, s1, 1);
        s1 += __shfl_xor_sync(0xffffffffu, s1, 2);
        float i0 = 1.f / s0, i1 = 1.f / s1;
#pragma unroll
        for (int nt = 0; nt < 6; nt++) {
            int c0 = nt*8 + 2*tg;
            psh[ r0     *PSS + c0    ] = f2tf(acc[mt][nt][0] * i0);
            psh[ r0     *PSS + c0 + 1] = f2tf(acc[mt][nt][1] * i0);
            psh[(r0 + 8)*PSS + c0    ] = f2tf(acc[mt][nt][2] * i1);
            psh[(r0 + 8)*PSS + c0 + 1] = f2tf(acc[mt][nt][3] * i1);
        }
    }
    __syncthreads();

    // ---- O = P @ V ----
    float oa[2][4][4];
#pragma unroll
    for (int a = 0; a < 2; a++)
#pragma unroll
        for (int b = 0; b < 4; b++)
#pragma unroll
            for (int c = 0; c < 4; c++) oa[a][b][c] = 0.f;

#pragma unroll
    for (int k = 0; k < 6; k++) {
        int kk = k*8;
        unsigned af[2][4], bf[4][2];
#pragma unroll
        for (int mt = 0; mt < 2; mt++) {
            int r = mb + mt*mstep + gid;
            af[mt][0] = psh[ r     *PSS + kk + tg];
            af[mt][1] = psh[(r + 8)*PSS + kk + tg];
            af[mt][2] = psh[ r     *PSS + kk + tg + 4];
            af[mt][3] = psh[(r + 8)*PSS + kk + tg + 4];
        }
#pragma unroll
        for (int nt = 0; nt < 4; nt++) {
            int n = hc + nt*8 + gid;
            bf[nt][0] = vt[n*PSS + kk + tg];
            bf[nt][1] = vt[n*PSS + kk + tg + 4];
        }
#pragma unroll
        for (int mt = 0; mt < 2; mt++)
#pragma unroll
            for (int nt = 0; nt < 4; nt++)
                mma_tf32(oa[mt][nt], af[mt], bf[nt]);
    }

#pragma unroll
    for (int mt = 0; mt < 2; mt++)
#pragma unroll
        for (int nt = 0; nt < 4; nt++) {
            int r = mb + mt*mstep + gid;
            int c = hc + nt*8 + 2*tg;
            if (r < NN)
                *(float2*)&o[((size_t)(fb*NN + r))*H + c] =
                    make_float2(oa[mt][nt][0], oa[mt][nt][1]);
            if (r + 8 < NN)
                *(float2*)&o[((size_t)(fb*NN + r + 8))*H + c] =
                    make_float2(oa[mt][nt][2], oa[mt][nt][3]);
        }
}

// ---------------- final LN over OUT=128 ----------------
__global__ __launch_bounds__(128) void lnf_k(const float* __restrict__ fin,
                                             const float* __restrict__ bo,
                                             const float* __restrict__ g,
                                             const float* __restrict__ b,
                                             float* __restrict__ out)
{
    int r = blockIdx.x, c = threadIdx.x;
    float v = fin[(size_t)r*OUTD + c] + bo[c];
    __shared__ float red[4];
    float s = v;
#pragma unroll
    for (int off = 16; off; off >>= 1) s += __shfl_xor_sync(0xffffffffu, s, off);
    if ((c & 31) == 0) red[c >> 5] = s;
    __syncthreads();
    float mu = (red[0] + red[1] + red[2] + red[3]) * (1.f/128.f);
    __syncthreads();
    float d = v - mu;
    float q = d * d;
#pragma unroll
    for (int off = 16; off; off >>= 1) q += __shfl_xor_sync(0xffffffffu, q, off);
    if ((c & 31) == 0) red[c >> 5] = q;
    __syncthreads();
    float var = (red[0] + red[1] + red[2] + red[3]) * (1.f/128.f);
    float rs = rsqrtf(var + 1e-5f);
    out[(size_t)r*OUTD + c] = d * rs * g[c] + b[c];
}

// ---------------- launch ----------------
extern "C" void kernel_launch(void* const* d_in, const int* in_sizes, int n_in,
                              void* d_out, int out_size)
{
    const float* forest = (const float*)d_in[0];
    const int*   adj    = (const int*)  d_in[1];
    const int*   order  = (const int*)  d_in[2];
    const float* W_in   = (const float*)d_in[3];
    const float* b_in   = (const float*)d_in[4];
    const float* qkv_w  = (const float*)d_in[5];
    const float* qkv_b  = (const float*)d_in[6];
    const float* aow    = (const float*)d_in[7];
    const float* aob    = (const float*)d_in[8];
    const float* f1w    = (const float*)d_in[9];
    const float* f1b    = (const float*)d_in[10];
    const float* f2w    = (const float*)d_in[11];
    const float* f2b    = (const float*)d_in[12];
    const float* ln1g   = (const float*)d_in[13];
    const float* ln1b   = (const float*)d_in[14];
    const float* ln2g   = (const float*)d_in[15];
    const float* ln2b   = (const float*)d_in[16];
    const float* Wout   = (const float*)d_in[17];
    const float* bout   = (const float*)d_in[18];
    const float* lnfg   = (const float*)d_in[19];
    const float* lnfb   = (const float*)d_in[20];

    float *px, *ppos, *pqkv, *pfin;
    cudaGetSymbolAddress((void**)&px,   g_x);
    cudaGetSymbolAddress((void**)&ppos, g_pos);
    cudaGetSymbolAddress((void**)&pqkv, g_qkv);
    cudaGetSymbolAddress((void**)&pfin, g_fin);

    cudaFuncSetAttribute(attn_k, cudaFuncAttributeMaxDynamicSharedMemorySize,
                         ATTN_SMEM_BYTES);

    // 1) positional encoding
    pos_kernel<<<FB, 128>>>(adj, order, ppos);

    // 2) embed: x = forest @ W_in^T + b_in + pos
    gemm_tc<EPI_ADD><<<dim3(TT/BM, 1, 1), 256>>>(
        forest, W_in, b_in, ppos, nullptr, nullptr, px, TT, H, NIN);

    for (int l = 0; l < LL; l++) {
        // qkv = x @ qkv_w^T + b    (N = 384)
        gemm_tc<EPI_BIAS><<<dim3(TT/BM, 3, 1), 256>>>(
            px, qkv_w + (size_t)l*3*H*H, qkv_b + (size_t)l*3*H,
            nullptr, nullptr, nullptr, pqkv, TT, 3*H, H);
        // attention -> ppos  (tensor-core)
        attn_k<<<FB, 256, ATTN_SMEM_BYTES>>>(pqkv, ppos);
        // x = LN( attn_out @ aow^T + aob + x )
        gemm_tc<EPI_LN><<<dim3(TT/BM, 1, 1), 256>>>(
            ppos, aow + (size_t)l*H*H, aob + (size_t)l*H, px,
            ln1g + (size_t)l*H, ln1b + (size_t)l*H, px, TT, H, H);
        // hidden = relu(x @ f1w^T + f1b)  (N = 256)
        gemm_tc<EPI_RELU><<<dim3(TT/BM, 2, 1), 256>>>(
            px, f1w + (size_t)l*FF*H, f1b + (size_t)l*FF,
            nullptr, nullptr, nullptr, pqkv, TT, FF, H);
        // x = LN( hidden @ f2w^T + f2b + x )
        gemm_tc<EPI_LN><<<dim3(TT/BM, 1, 1), 256>>>(
            pqkv, f2w + (size_t)l*H*FF, f2b + (size_t)l*H, px,
            ln2g + (size_t)l*H, ln2b + (size_t)l*H, px, TT, H, FF);
    }

    // 3) final: out = LN( x.reshape(FB, NN*H) @ Wout^T + b_out )
    cudaMemsetAsync(pfin, 0, (size_t)FB*OUTD*sizeof(float));
    gemm_tc<EPI_ATOMIC><<<dim3(FB/BM, 1, 8), 256>>>(
        px, Wout, nullptr, nullptr, nullptr, nullptr, pfin, FB, OUTD, NN*H);
    lnf_k<<<FB, 128>>>(pfin, bout, lnfg, lnfb, (float*)d_out);
}